// round 11
// baseline (speedup 1.0000x reference)
#include <cuda_runtime.h>
#include <cuda_fp16.h>

// Problem constants
#define BATCH    128
#define SEQT     256
#define HID      128
#define WIN      16
#define NSTEP    3840          // (256-16)*16 chained LSTM steps
#define NTHREADS 512           // 16 warps; warp w owns gate rows [32w, 32w+32)

// Named barriers:
//   1: sg ready  (producers arrive, combiners sync)
//   2: h ready   (combiners arrive, producers sync)
//   3: combiner-only sync (128 threads) before next-step MMA issue
#define BAR_ARRIVE(id, n) asm volatile("bar.arrive %0, %1;" :: "r"(id), "r"(n) : "memory")
#define BAR_SYNC(id, n)   asm volatile("bar.sync %0, %1;"   :: "r"(id), "r"(n) : "memory")

// HW tanh (MUFU.TANH) and sigmoid via tanh
__device__ __forceinline__ float tanh_fast(float x) {
    float y; asm("tanh.approx.f32 %0, %1;" : "=f"(y) : "f"(x)); return y;
}
__device__ __forceinline__ float sigm_fast(float x) {
    return __fmaf_rn(0.5f, tanh_fast(0.5f * x), 0.5f);
}
__device__ __forceinline__ unsigned pack_h2(float lo, float hi) {
    __half2 h = __floats2half2_rn(lo, hi);
    return *reinterpret_cast<unsigned*>(&h);
}
// m16n8k16 row.col f16*f16 -> f32 accumulate (warp-level HMMA)
__device__ __forceinline__ void mma16816(float* c, const unsigned* a, unsigned b0, unsigned b1) {
    asm volatile(
        "mma.sync.aligned.m16n8k16.row.col.f32.f16.f16.f32 "
        "{%0,%1,%2,%3},{%4,%5,%6,%7},{%8,%9},{%0,%1,%2,%3};\n"
        : "+f"(c[0]), "+f"(c[1]), "+f"(c[2]), "+f"(c[3])
        : "r"(a[0]), "r"(a[1]), "r"(a[2]), "r"(a[3]), "r"(b0), "r"(b1));
}

__global__ void __launch_bounds__(NTHREADS, 1)
lstm_mma9_kernel(const float* __restrict__ x,
                 const float* __restrict__ W_ih,
                 const float* __restrict__ W_hh,
                 const float* __restrict__ b_ih,
                 const float* __restrict__ b_hh,
                 const float* __restrict__ fc_W,
                 const float* __restrict__ fc_b,
                 float* __restrict__ out)
{
    __shared__ float sx[SEQT];
    __shared__ float sg[4 * HID];                 // raw gates, row-major
    // h in B-FRAGMENT ORDER: u32 slot (kk*8 + tg*2 + b3) = half2 for
    // k = 16kk + 8*b3 + 2tg (+1). b0/b1 of one k-step are adjacent -> LDS.64.
    __shared__ __align__(16) unsigned shB_hi[64]; // 128 halves (h high part)
    __shared__ __align__(16) unsigned shB_lo[64]; // 128 halves (h residual)
    __shared__ float sred[4];

    const int tid = threadIdx.x;
    const int b   = blockIdx.x;
    const int w   = tid >> 5;          // warp 0..15
    const int l   = tid & 31;
    const int gid = l >> 2;            // 0..7  (frag row group / B column)
    const int tg  = l & 3;             // 0..3
    const bool combiner = (w >= 12);   // warps 12-15 run the cell combine
    const int  cu = tid - 384;         // combiner's hidden unit (0..127)

    // ---------------- Prologue: A fragments (W_hh fp16, resident in RF) ----
    unsigned Afrag[2][8][4];
#pragma unroll
    for (int t = 0; t < 2; ++t) {
        const int R = 32 * w + 16 * t;
        const float* r0 = W_hh + (R + gid)     * HID;
        const float* r8 = W_hh + (R + gid + 8) * HID;
#pragma unroll
        for (int kk = 0; kk < 8; ++kk) {
            const int k0 = 16 * kk + 2 * tg;
            Afrag[t][kk][0] = pack_h2(r0[k0],     r0[k0 + 1]);
            Afrag[t][kk][1] = pack_h2(r8[k0],     r8[k0 + 1]);
            Afrag[t][kk][2] = pack_h2(r0[k0 + 8], r0[k0 + 9]);
            Afrag[t][kk][3] = pack_h2(r8[k0 + 8], r8[k0 + 9]);
        }
    }

    // Per-lane bias / W_ih for rows (gid, gid+8) of each tile (used at tg==0)
    float biasr[2][2], wihr[2][2];
#pragma unroll
    for (int t = 0; t < 2; ++t) {
        const int R = 32 * w + 16 * t;
        biasr[t][0] = b_ih[R + gid]     + b_hh[R + gid];
        biasr[t][1] = b_ih[R + gid + 8] + b_hh[R + gid + 8];
        wihr[t][0]  = W_ih[R + gid];
        wihr[t][1]  = W_ih[R + gid + 8];
    }

    const float fcw = combiner ? fc_W[cu] : 0.f;
    const float fcb = fc_b[0];
    float c_state = 0.f;

    if (tid < 64) { shB_hi[tid] = 0u; shB_lo[tid] = 0u; }    // h0 = 0
    if (tid < SEQT) sx[tid] = x[b * SEQT + tid];
    if (tid < WIN)  out[b * SEQT + tid] = x[b * SEQT + tid];
    __syncthreads();

    // Combiner's h-store byte offset in the fragment-ordered buffer:
    //   kk=cu>>4, b3=(cu>>3)&1, tg=(cu>>1)&3, e=cu&1
    const int frag_off = combiner
        ? (((cu >> 4) << 5) + (((cu >> 1) & 3) << 3) + (((cu >> 3) & 1) << 2) + ((cu & 1) << 1))
        : 0;
    __half* sthi = (__half*)((char*)shB_hi + frag_off);
    __half* stlo = (__half*)((char*)shB_lo + frag_off);

    // B-operand base: column gid==1 reads h_lo; all others read h_hi
    const char* bpc = (const char*)((gid == 1) ? shB_lo : shB_hi);

    // Prefetched per-step init: x*W_ih + bias for this lane's rows (tg==0 only)
    float init_[2][2];
    {
        const float xt0 = sx[0];
#pragma unroll
        for (int t = 0; t < 2; ++t) {
            init_[t][0] = __fmaf_rn(xt0, wihr[t][0], biasr[t][0]);
            init_[t][1] = __fmaf_rn(xt0, wihr[t][1], biasr[t][1]);
        }
    }

    // ---------------- 3840 chained steps -----------------------------------
    for (int s = 0; s < NSTEP; ++s) {
        // Two half-depth chains per tile: cA (kk 0..3) + cB (kk 4..7).
        float cA[2][4], cB[2][4];
#pragma unroll
        for (int t = 0; t < 2; ++t) {
            if (tg == 0) { cA[t][0] = init_[t][0]; cA[t][2] = init_[t][1]; }
            else         { cA[t][0] = 0.f;         cA[t][2] = 0.f; }
            cA[t][1] = 0.f; cA[t][3] = 0.f;
            cB[t][0] = 0.f; cB[t][1] = 0.f; cB[t][2] = 0.f; cB[t][3] = 0.f;
        }

        // One LDS.64 per k-step fetches {b0, b1}.
#pragma unroll
        for (int kk = 0; kk < 4; ++kk) {
            const uint2 bb = *(const uint2*)(bpc + kk * 32 + tg * 8);
            mma16816(cA[0], Afrag[0][kk], bb.x, bb.y);
            mma16816(cA[1], Afrag[1][kk], bb.x, bb.y);
        }
#pragma unroll
        for (int kk = 4; kk < 8; ++kk) {
            const uint2 bb = *(const uint2*)(bpc + kk * 32 + tg * 8);
            mma16816(cB[0], Afrag[0][kk], bb.x, bb.y);
            mma16816(cB[1], Afrag[1][kk], bb.x, bb.y);
        }

        // tg==0 lanes: raw gate = (col0 hi) + (col1 lo).
        if (tg == 0) {
#pragma unroll
            for (int t = 0; t < 2; ++t) {
                const int R = 32 * w + 16 * t;
                sg[R + gid]     = (cA[t][0] + cB[t][0]) + (cA[t][1] + cB[t][1]);
                sg[R + gid + 8] = (cA[t][2] + cB[t][2]) + (cA[t][3] + cB[t][3]);
            }
        }

        // Prefetch next step's init (h-independent) before blocking.
        {
            const int s1 = s + 1;
            const float xt1 = sx[(s1 >> 4) + (s1 & (WIN - 1))];
#pragma unroll
            for (int t = 0; t < 2; ++t) {
                init_[t][0] = __fmaf_rn(xt1, wihr[t][0], biasr[t][0]);
                init_[t][1] = __fmaf_rn(xt1, wihr[t][1], biasr[t][1]);
            }
        }

        if (!combiner) {
            // Producers: post sg, then block once until h is ready.
            BAR_ARRIVE(1, NTHREADS);
            BAR_SYNC(2, NTHREADS);
        } else {
            // Combiners (warps 12-15): wait for sg.
            BAR_SYNC(1, NTHREADS);

            const float gi = sg[cu];
            const float gf = sg[cu + HID];
            const float gg = sg[cu + 2 * HID];
            const float go = sg[cu + 3 * HID];
            c_state = sigm_fast(gf) * c_state + sigm_fast(gi) * tanh_fast(gg);
            const float h = sigm_fast(go) * tanh_fast(c_state);

            const __half hh = __float2half_rn(h);
            *sthi = hh;
            *stlo = __float2half_rn(h - __half2float(hh));

            const bool tap = ((s & (WIN - 1)) == (WIN - 1));
            if (tap) {                                     // fc tap at t=15
                float p = fcw * h;
                p += __shfl_down_sync(0xffffffffu, p, 16);
                p += __shfl_down_sync(0xffffffffu, p, 8);
                p += __shfl_down_sync(0xffffffffu, p, 4);
                p += __shfl_down_sync(0xffffffffu, p, 2);
                p += __shfl_down_sync(0xffffffffu, p, 1);
                if (l == 0) sred[w - 12] = p;
            }

            // Release producers (non-blocking), then sync only the 4
            // combiner warps and launch next step's MMAs immediately.
            BAR_ARRIVE(2, NTHREADS);
            BAR_SYNC(3, 128);

            if (tap && tid == 384) {
                float v = sred[0] + sred[1] + sred[2] + sred[3] + fcb;
                out[b * SEQT + WIN + (s >> 4)] = (v >= 0.f) ? v : 0.3f * v;
            }
        }
    }
}

extern "C" void kernel_launch(void* const* d_in, const int* in_sizes, int n_in,
                              void* d_out, int out_size)
{
    const float* x    = (const float*)d_in[0];
    const float* W_ih = (const float*)d_in[1];
    const float* W_hh = (const float*)d_in[2];
    const float* b_ih = (const float*)d_in[3];
    const float* b_hh = (const float*)d_in[4];
    const float* fc_W = (const float*)d_in[5];
    const float* fc_b = (const float*)d_in[6];

    lstm_mma9_kernel<<<BATCH, NTHREADS>>>(
        x, W_ih, W_hh, b_ih, b_hh, fc_W, fc_b, (float*)d_out);
}

// round 12
// speedup vs baseline: 1.0120x; 1.0120x over previous
#include <cuda_runtime.h>
#include <cuda_fp16.h>

// Problem constants
#define BATCH    128
#define SEQT     256
#define HID      128
#define WIN      16
#define NSTEP    3840          // (256-16)*16 chained LSTM steps
#define NTHREADS 512           // 16 warps; warp w owns gate rows [32w, 32w+32)

// Named barriers (1: sg ready -> combine; 2: h ready -> everyone)
#define BAR_ARRIVE(id) asm volatile("bar.arrive %0, %1;" :: "r"(id), "r"(NTHREADS) : "memory")
#define BAR_SYNC(id)   asm volatile("bar.sync %0, %1;"   :: "r"(id), "r"(NTHREADS) : "memory")

// HW tanh (MUFU.TANH) and sigmoid via tanh
__device__ __forceinline__ float tanh_fast(float x) {
    float y; asm("tanh.approx.f32 %0, %1;" : "=f"(y) : "f"(x)); return y;
}
__device__ __forceinline__ float sigm_fast(float x) {
    return __fmaf_rn(0.5f, tanh_fast(0.5f * x), 0.5f);
}
__device__ __forceinline__ unsigned pack_h2(float lo, float hi) {
    __half2 h = __floats2half2_rn(lo, hi);
    return *reinterpret_cast<unsigned*>(&h);
}
// m16n8k16 row.col f16*f16 -> f32 accumulate (warp-level HMMA)
__device__ __forceinline__ void mma16816(float* c, const unsigned* a, unsigned b0, unsigned b1) {
    asm volatile(
        "mma.sync.aligned.m16n8k16.row.col.f32.f16.f16.f32 "
        "{%0,%1,%2,%3},{%4,%5,%6,%7},{%8,%9},{%0,%1,%2,%3};\n"
        : "+f"(c[0]), "+f"(c[1]), "+f"(c[2]), "+f"(c[3])
        : "r"(a[0]), "r"(a[1]), "r"(a[2]), "r"(a[3]), "r"(b0), "r"(b1));
}

__global__ void __launch_bounds__(NTHREADS, 1)
lstm_mma10_kernel(const float* __restrict__ x,
                  const float* __restrict__ W_ih,
                  const float* __restrict__ W_hh,
                  const float* __restrict__ b_ih,
                  const float* __restrict__ b_hh,
                  const float* __restrict__ fc_W,
                  const float* __restrict__ fc_b,
                  float* __restrict__ out)
{
    __shared__ float sx[SEQT];
    // Permuted raw-gate buffer: slot(r) = (r & ~15) + ((r&7)<<1) + ((r>>3)&1)
    // -> rows R+gid and R+gid+8 are ADJACENT floats (one STS.64 per tile).
    __shared__ __align__(16) float sg[4 * HID];
    // h in B-FRAGMENT ORDER: u32 slot (kk*8 + tg*2 + b3) = half2 for
    // k = 16kk + 8*b3 + 2tg (+1). b0/b1 of one k-step are adjacent -> LDS.64.
    __shared__ __align__(16) unsigned shB_hi[64]; // 128 halves (h high part)
    __shared__ __align__(16) unsigned shB_lo[64]; // 128 halves (h residual)
    __shared__ float sred[4];

    const int tid = threadIdx.x;
    const int b   = blockIdx.x;
    const int w   = tid >> 5;          // warp 0..15
    const int l   = tid & 31;
    const int gid = l >> 2;            // 0..7  (frag row group / B column)
    const int tg  = l & 3;             // 0..3
    const bool combiner = (w >= 12);   // warps 12-15 run the cell combine
    const int  cu = tid - 384;         // combiner's hidden unit (0..127)

    // ---------------- Prologue: A fragments (W_hh fp16, resident in RF) ----
    unsigned Afrag[2][8][4];
#pragma unroll
    for (int t = 0; t < 2; ++t) {
        const int R = 32 * w + 16 * t;
        const float* r0 = W_hh + (R + gid)     * HID;
        const float* r8 = W_hh + (R + gid + 8) * HID;
#pragma unroll
        for (int kk = 0; kk < 8; ++kk) {
            const int k0 = 16 * kk + 2 * tg;
            Afrag[t][kk][0] = pack_h2(r0[k0],     r0[k0 + 1]);
            Afrag[t][kk][1] = pack_h2(r8[k0],     r8[k0 + 1]);
            Afrag[t][kk][2] = pack_h2(r0[k0 + 8], r0[k0 + 9]);
            Afrag[t][kk][3] = pack_h2(r8[k0 + 8], r8[k0 + 9]);
        }
    }

    // Per-lane bias / W_ih for rows (gid, gid+8) of each tile (used at tg==0)
    float biasr[2][2], wihr[2][2];
#pragma unroll
    for (int t = 0; t < 2; ++t) {
        const int R = 32 * w + 16 * t;
        biasr[t][0] = b_ih[R + gid]     + b_hh[R + gid];
        biasr[t][1] = b_ih[R + gid + 8] + b_hh[R + gid + 8];
        wihr[t][0]  = W_ih[R + gid];
        wihr[t][1]  = W_ih[R + gid + 8];
    }

    const float fcw = combiner ? fc_W[cu] : 0.f;
    const float fcb = fc_b[0];
    float c_state = 0.f;

    if (tid < 64) { shB_hi[tid] = 0u; shB_lo[tid] = 0u; }    // h0 = 0
    if (tid < SEQT) sx[tid] = x[b * SEQT + tid];
    if (tid < WIN)  out[b * SEQT + tid] = x[b * SEQT + tid];
    __syncthreads();

    // Combiner's h-store byte offset in the fragment-ordered buffer:
    //   kk=cu>>4, b3=(cu>>3)&1, tg=(cu>>1)&3, e=cu&1
    const int frag_off = combiner
        ? (((cu >> 4) << 5) + (((cu >> 1) & 3) << 3) + (((cu >> 3) & 1) << 2) + ((cu & 1) << 1))
        : 0;
    __half* sthi = (__half*)((char*)shB_hi + frag_off);
    __half* stlo = (__half*)((char*)shB_lo + frag_off);

    // Combiner's permuted gate-slot index: q = slot(cu); gates at q + 128*g.
    const int q = combiner
        ? ((cu & ~15) + ((cu & 7) << 1) + ((cu >> 3) & 1))
        : 0;

    // Producer's paired-store slot (float2 index): rows (R+gid, R+gid+8)
    // live at float offset 32w+16t+2gid -> float2 index 16w+8t+gid.
    float2* sg2 = (float2*)sg;

    // B-operand base: column gid==1 reads h_lo; all others read h_hi
    const char* bpc = (const char*)((gid == 1) ? shB_lo : shB_hi);

    // Prefetched per-step init: x*W_ih + bias for this lane's rows
    float init_[2][2];
    {
        const float xt0 = sx[0];
#pragma unroll
        for (int t = 0; t < 2; ++t) {
            init_[t][0] = __fmaf_rn(xt0, wihr[t][0], biasr[t][0]);
            init_[t][1] = __fmaf_rn(xt0, wihr[t][1], biasr[t][1]);
        }
    }

    // ---------------- 3840 chained steps -----------------------------------
    for (int s = 0; s < NSTEP; ++s) {
        // Two half-depth chains per tile: cA (kk 0..3) + cB (kk 4..7).
        float cA[2][4], cB[2][4];
#pragma unroll
        for (int t = 0; t < 2; ++t) {
            if (tg == 0) { cA[t][0] = init_[t][0]; cA[t][2] = init_[t][1]; }
            else         { cA[t][0] = 0.f;         cA[t][2] = 0.f; }
            cA[t][1] = 0.f; cA[t][3] = 0.f;
            cB[t][0] = 0.f; cB[t][1] = 0.f; cB[t][2] = 0.f; cB[t][3] = 0.f;
        }

        // One LDS.64 per k-step fetches {b0, b1}.
#pragma unroll
        for (int kk = 0; kk < 4; ++kk) {
            const uint2 bb = *(const uint2*)(bpc + kk * 32 + tg * 8);
            mma16816(cA[0], Afrag[0][kk], bb.x, bb.y);
            mma16816(cA[1], Afrag[1][kk], bb.x, bb.y);
        }
#pragma unroll
        for (int kk = 4; kk < 8; ++kk) {
            const uint2 bb = *(const uint2*)(bpc + kk * 32 + tg * 8);
            mma16816(cB[0], Afrag[0][kk], bb.x, bb.y);
            mma16816(cB[1], Afrag[1][kk], bb.x, bb.y);
        }

        // tg==0 lanes: raw gate = (col0 hi) + (col1 lo); one STS.64 per tile.
        if (tg == 0) {
#pragma unroll
            for (int t = 0; t < 2; ++t) {
                const float v0 = (cA[t][0] + cB[t][0]) + (cA[t][1] + cB[t][1]);
                const float v1 = (cA[t][2] + cB[t][2]) + (cA[t][3] + cB[t][3]);
                sg2[16 * w + 8 * t + gid] = make_float2(v0, v1);
            }
        }

        // Prefetch next step's init (h-independent) before blocking.
        {
            const int s1 = s + 1;
            const float xt1 = sx[(s1 >> 4) + (s1 & (WIN - 1))];
#pragma unroll
            for (int t = 0; t < 2; ++t) {
                init_[t][0] = __fmaf_rn(xt1, wihr[t][0], biasr[t][0]);
                init_[t][1] = __fmaf_rn(xt1, wihr[t][1], biasr[t][1]);
            }
        }

        if (!combiner) {
            // Producers: post sg, then block once until h is ready.
            BAR_ARRIVE(1);
            BAR_SYNC(2);
        } else {
            // Combiners (warps 12-15, highest arbiter priority): wait for sg.
            BAR_SYNC(1);

            const float gi = sg[q];
            const float gf = sg[q + HID];
            const float gg = sg[q + 2 * HID];
            const float go = sg[q + 3 * HID];
            c_state = sigm_fast(gf) * c_state + sigm_fast(gi) * tanh_fast(gg);
            const float h = sigm_fast(go) * tanh_fast(c_state);

            const __half hh = __float2half_rn(h);
            *sthi = hh;
            *stlo = __float2half_rn(h - __half2float(hh));

            if ((s & (WIN - 1)) == (WIN - 1)) {            // fc tap at t=15
                float p = fcw * h;
                p += __shfl_down_sync(0xffffffffu, p, 16);
                p += __shfl_down_sync(0xffffffffu, p, 8);
                p += __shfl_down_sync(0xffffffffu, p, 4);
                p += __shfl_down_sync(0xffffffffu, p, 2);
                p += __shfl_down_sync(0xffffffffu, p, 1);
                if (l == 0) sred[w - 12] = p;
            }
            BAR_SYNC(2);

            if (((s & (WIN - 1)) == (WIN - 1)) && tid == 384) {
                float v = sred[0] + sred[1] + sred[2] + sred[3] + fcb;
                out[b * SEQT + WIN + (s >> 4)] = (v >= 0.f) ? v : 0.3f * v;
            }
        }
    }
}

extern "C" void kernel_launch(void* const* d_in, const int* in_sizes, int n_in,
                              void* d_out, int out_size)
{
    const float* x    = (const float*)d_in[0];
    const float* W_ih = (const float*)d_in[1];
    const float* W_hh = (const float*)d_in[2];
    const float* b_ih = (const float*)d_in[3];
    const float* b_hh = (const float*)d_in[4];
    const float* fc_W = (const float*)d_in[5];
    const float* fc_b = (const float*)d_in[6];

    lstm_mma10_kernel<<<BATCH, NTHREADS>>>(
        x, W_ih, W_hh, b_ih, b_hh, fc_W, fc_b, (float*)d_out);
}

// round 13
// speedup vs baseline: 1.0746x; 1.0619x over previous
#include <cuda_runtime.h>
#include <cuda_fp16.h>

// Problem constants
#define BATCH    128
#define SEQT     256
#define HID      128
#define WIN      16
#define NSTEP    3840          // (256-16)*16 chained LSTM steps
#define NTHREADS 256           // 8 warps; warp w owns gate rows [64w, 64w+64)

// Named barriers (1: sg ready -> combine; 2: h ready -> everyone)
#define BAR_ARRIVE(id) asm volatile("bar.arrive %0, %1;" :: "r"(id), "r"(NTHREADS) : "memory")
#define BAR_SYNC(id)   asm volatile("bar.sync %0, %1;"   :: "r"(id), "r"(NTHREADS) : "memory")

// HW tanh (MUFU.TANH) and sigmoid via tanh
__device__ __forceinline__ float tanh_fast(float x) {
    float y; asm("tanh.approx.f32 %0, %1;" : "=f"(y) : "f"(x)); return y;
}
__device__ __forceinline__ float sigm_fast(float x) {
    return __fmaf_rn(0.5f, tanh_fast(0.5f * x), 0.5f);
}
__device__ __forceinline__ unsigned pack_h2(float lo, float hi) {
    __half2 h = __floats2half2_rn(lo, hi);
    return *reinterpret_cast<unsigned*>(&h);
}
// m16n8k16 row.col f16*f16 -> f32 accumulate (warp-level HMMA)
__device__ __forceinline__ void mma16816(float* c, const unsigned* a, unsigned b0, unsigned b1) {
    asm volatile(
        "mma.sync.aligned.m16n8k16.row.col.f32.f16.f16.f32 "
        "{%0,%1,%2,%3},{%4,%5,%6,%7},{%8,%9},{%0,%1,%2,%3};\n"
        : "+f"(c[0]), "+f"(c[1]), "+f"(c[2]), "+f"(c[3])
        : "r"(a[0]), "r"(a[1]), "r"(a[2]), "r"(a[3]), "r"(b0), "r"(b1));
}

__global__ void __launch_bounds__(NTHREADS, 1)
lstm_mma11_kernel(const float* __restrict__ x,
                  const float* __restrict__ W_ih,
                  const float* __restrict__ W_hh,
                  const float* __restrict__ b_ih,
                  const float* __restrict__ b_hh,
                  const float* __restrict__ fc_W,
                  const float* __restrict__ fc_b,
                  float* __restrict__ out)
{
    __shared__ float sx[SEQT];
    // Permuted raw-gate buffer: slot(r) = (r & ~15) + ((r&7)<<1) + ((r>>3)&1)
    // -> rows R+gid and R+gid+8 are ADJACENT floats (one STS.64 per tile).
    __shared__ __align__(16) float sg[4 * HID];
    // h in B-FRAGMENT ORDER: u32 slot (kk*8 + tg*2 + b3) = half2 for
    // k = 16kk + 8*b3 + 2tg (+1). b0/b1 of one k-step are adjacent -> LDS.64.
    __shared__ __align__(16) unsigned shB_hi[64]; // 128 halves (h high part)
    __shared__ __align__(16) unsigned shB_lo[64]; // 128 halves (h residual)
    __shared__ float sred[4];

    const int tid = threadIdx.x;
    const int b   = blockIdx.x;
    const int w   = tid >> 5;          // warp 0..7
    const int l   = tid & 31;
    const int gid = l >> 2;            // 0..7  (frag row group / B column)
    const int tg  = l & 3;             // 0..3
    const bool combiner = (w >= 4);    // warps 4-7 run the cell combine
    const int  cu = tid - 128;         // combiner's hidden unit (0..127)

    // ---------------- Prologue: A fragments (W_hh fp16, resident in RF) ----
    // Warp w owns 4 tiles: gate rows R..R+15, R = 64w + 16t, t = 0..3.
    unsigned Afrag[4][8][4];
#pragma unroll
    for (int t = 0; t < 4; ++t) {
        const int R = 64 * w + 16 * t;
        const float* r0 = W_hh + (R + gid)     * HID;
        const float* r8 = W_hh + (R + gid + 8) * HID;
#pragma unroll
        for (int kk = 0; kk < 8; ++kk) {
            const int k0 = 16 * kk + 2 * tg;
            Afrag[t][kk][0] = pack_h2(r0[k0],     r0[k0 + 1]);
            Afrag[t][kk][1] = pack_h2(r8[k0],     r8[k0 + 1]);
            Afrag[t][kk][2] = pack_h2(r0[k0 + 8], r0[k0 + 9]);
            Afrag[t][kk][3] = pack_h2(r8[k0 + 8], r8[k0 + 9]);
        }
    }

    // Per-lane bias / W_ih for rows (gid, gid+8) of each tile (used at tg==0)
    float biasr[4][2], wihr[4][2];
#pragma unroll
    for (int t = 0; t < 4; ++t) {
        const int R = 64 * w + 16 * t;
        biasr[t][0] = b_ih[R + gid]     + b_hh[R + gid];
        biasr[t][1] = b_ih[R + gid + 8] + b_hh[R + gid + 8];
        wihr[t][0]  = W_ih[R + gid];
        wihr[t][1]  = W_ih[R + gid + 8];
    }

    const float fcw = combiner ? fc_W[cu] : 0.f;
    const float fcb = fc_b[0];
    float c_state = 0.f;

    if (tid < 64) { shB_hi[tid] = 0u; shB_lo[tid] = 0u; }    // h0 = 0
    sx[tid] = x[b * SEQT + tid];                             // 256 threads = SEQT
    if (tid < WIN)  out[b * SEQT + tid] = x[b * SEQT + tid];
    __syncthreads();

    // Combiner's h-store byte offset in the fragment-ordered buffer:
    //   kk=cu>>4, b3=(cu>>3)&1, tg=(cu>>1)&3, e=cu&1
    const int frag_off = combiner
        ? (((cu >> 4) << 5) + (((cu >> 1) & 3) << 3) + (((cu >> 3) & 1) << 2) + ((cu & 1) << 1))
        : 0;
    __half* sthi = (__half*)((char*)shB_hi + frag_off);
    __half* stlo = (__half*)((char*)shB_lo + frag_off);

    // Combiner's permuted gate-slot index: q = slot(cu); gates at q + 128*g.
    const int q = combiner
        ? ((cu & ~15) + ((cu & 7) << 1) + ((cu >> 3) & 1))
        : 0;

    // Producer's paired-store slot (float2 index): rows (R+gid, R+gid+8)
    // live at float offset 64w+16t+2gid -> float2 index 32w+8t+gid.
    float2* sg2 = (float2*)sg;

    // B-operand base: column gid==1 reads h_lo; all others read h_hi
    const char* bpc = (const char*)((gid == 1) ? shB_lo : shB_hi);

    // Prefetched per-step init: x*W_ih + bias for this lane's rows
    float init_[4][2];
    {
        const float xt0 = sx[0];
#pragma unroll
        for (int t = 0; t < 4; ++t) {
            init_[t][0] = __fmaf_rn(xt0, wihr[t][0], biasr[t][0]);
            init_[t][1] = __fmaf_rn(xt0, wihr[t][1], biasr[t][1]);
        }
    }

    // ---------------- 3840 chained steps -----------------------------------
    for (int s = 0; s < NSTEP; ++s) {
        // Eight half-depth chains: cA[t] (kk 0..3) + cB[t] (kk 4..7), t=0..3.
        float cA[4][4], cB[4][4];
#pragma unroll
        for (int t = 0; t < 4; ++t) {
            if (tg == 0) { cA[t][0] = init_[t][0]; cA[t][2] = init_[t][1]; }
            else         { cA[t][0] = 0.f;         cA[t][2] = 0.f; }
            cA[t][1] = 0.f; cA[t][3] = 0.f;
            cB[t][0] = 0.f; cB[t][1] = 0.f; cB[t][2] = 0.f; cB[t][3] = 0.f;
        }

        // One LDS.64 per k-step fetches {b0, b1}; 4 MMAs (one per tile) each.
#pragma unroll
        for (int kk = 0; kk < 4; ++kk) {
            const uint2 bb = *(const uint2*)(bpc + kk * 32 + tg * 8);
            mma16816(cA[0], Afrag[0][kk], bb.x, bb.y);
            mma16816(cA[1], Afrag[1][kk], bb.x, bb.y);
            mma16816(cA[2], Afrag[2][kk], bb.x, bb.y);
            mma16816(cA[3], Afrag[3][kk], bb.x, bb.y);
        }
#pragma unroll
        for (int kk = 4; kk < 8; ++kk) {
            const uint2 bb = *(const uint2*)(bpc + kk * 32 + tg * 8);
            mma16816(cB[0], Afrag[0][kk], bb.x, bb.y);
            mma16816(cB[1], Afrag[1][kk], bb.x, bb.y);
            mma16816(cB[2], Afrag[2][kk], bb.x, bb.y);
            mma16816(cB[3], Afrag[3][kk], bb.x, bb.y);
        }

        // tg==0 lanes: raw gate = (col0 hi) + (col1 lo); one STS.64 per tile.
        if (tg == 0) {
#pragma unroll
            for (int t = 0; t < 4; ++t) {
                const float v0 = (cA[t][0] + cB[t][0]) + (cA[t][1] + cB[t][1]);
                const float v1 = (cA[t][2] + cB[t][2]) + (cA[t][3] + cB[t][3]);
                sg2[32 * w + 8 * t + gid] = make_float2(v0, v1);
            }
        }

        // Prefetch next step's init (h-independent) before blocking.
        {
            const int s1 = s + 1;
            const float xt1 = sx[(s1 >> 4) + (s1 & (WIN - 1))];
#pragma unroll
            for (int t = 0; t < 4; ++t) {
                init_[t][0] = __fmaf_rn(xt1, wihr[t][0], biasr[t][0]);
                init_[t][1] = __fmaf_rn(xt1, wihr[t][1], biasr[t][1]);
            }
        }

        if (!combiner) {
            // Producers: post sg, then block once until h is ready.
            BAR_ARRIVE(1);
            BAR_SYNC(2);
        } else {
            // Combiners (warps 4-7, highest arbiter priority): wait for sg.
            BAR_SYNC(1);

            const float gi = sg[q];
            const float gf = sg[q + HID];
            const float gg = sg[q + 2 * HID];
            const float go = sg[q + 3 * HID];
            c_state = sigm_fast(gf) * c_state + sigm_fast(gi) * tanh_fast(gg);
            const float h = sigm_fast(go) * tanh_fast(c_state);

            const __half hh = __float2half_rn(h);
            *sthi = hh;
            *stlo = __float2half_rn(h - __half2float(hh));

            if ((s & (WIN - 1)) == (WIN - 1)) {            // fc tap at t=15
                float p = fcw * h;
                p += __shfl_down_sync(0xffffffffu, p, 16);
                p += __shfl_down_sync(0xffffffffu, p, 8);
                p += __shfl_down_sync(0xffffffffu, p, 4);
                p += __shfl_down_sync(0xffffffffu, p, 2);
                p += __shfl_down_sync(0xffffffffu, p, 1);
                if (l == 0) sred[w - 4] = p;
            }
            BAR_SYNC(2);

            if (((s & (WIN - 1)) == (WIN - 1)) && tid == 128) {
                float v = sred[0] + sred[1] + sred[2] + sred[3] + fcb;
                out[b * SEQT + WIN + (s >> 4)] = (v >= 0.f) ? v : 0.3f * v;
            }
        }
    }
}

extern "C" void kernel_launch(void* const* d_in, const int* in_sizes, int n_in,
                              void* d_out, int out_size)
{
    const float* x    = (const float*)d_in[0];
    const float* W_ih = (const float*)d_in[1];
    const float* W_hh = (const float*)d_in[2];
    const float* b_ih = (const float*)d_in[3];
    const float* b_hh = (const float*)d_in[4];
    const float* fc_W = (const float*)d_in[5];
    const float* fc_b = (const float*)d_in[6];

    lstm_mma11_kernel<<<BATCH, NTHREADS>>>(
        x, W_ih, W_hh, b_ih, b_hh, fc_W, fc_b, (float*)d_out);
}

// round 14
// speedup vs baseline: 1.0949x; 1.0189x over previous
#include <cuda_runtime.h>
#include <cuda_fp16.h>

// Problem constants
#define BATCH    128
#define SEQT     256
#define HID      128
#define WIN      16
#define NSTEP    3840          // (256-16)*16 chained LSTM steps
#define NTHREADS 256           // 8 warps; warp w owns gate rows [64w, 64w+64)

// Named barriers (1: sg ready -> combine; 2: h ready -> everyone)
#define BAR_ARRIVE(id) asm volatile("bar.arrive %0, %1;" :: "r"(id), "r"(NTHREADS) : "memory")
#define BAR_SYNC(id)   asm volatile("bar.sync %0, %1;"   :: "r"(id), "r"(NTHREADS) : "memory")

// HW tanh (MUFU.TANH) and sigmoid via tanh
__device__ __forceinline__ float tanh_fast(float x) {
    float y; asm("tanh.approx.f32 %0, %1;" : "=f"(y) : "f"(x)); return y;
}
__device__ __forceinline__ float sigm_fast(float x) {
    return __fmaf_rn(0.5f, tanh_fast(0.5f * x), 0.5f);
}
__device__ __forceinline__ unsigned pack_h2(float lo, float hi) {
    __half2 h = __floats2half2_rn(lo, hi);
    return *reinterpret_cast<unsigned*>(&h);
}
// m16n8k16 row.col f16*f16 -> f32 accumulate (warp-level HMMA)
__device__ __forceinline__ void mma16816(float* c, const unsigned* a, unsigned b0, unsigned b1) {
    asm volatile(
        "mma.sync.aligned.m16n8k16.row.col.f32.f16.f16.f32 "
        "{%0,%1,%2,%3},{%4,%5,%6,%7},{%8,%9},{%0,%1,%2,%3};\n"
        : "+f"(c[0]), "+f"(c[1]), "+f"(c[2]), "+f"(c[3])
        : "r"(a[0]), "r"(a[1]), "r"(a[2]), "r"(a[3]), "r"(b0), "r"(b1));
}

__global__ void __launch_bounds__(NTHREADS, 1)
lstm_mma12_kernel(const float* __restrict__ x,
                  const float* __restrict__ W_ih,
                  const float* __restrict__ W_hh,
                  const float* __restrict__ b_ih,
                  const float* __restrict__ b_hh,
                  const float* __restrict__ fc_W,
                  const float* __restrict__ fc_b,
                  float* __restrict__ out)
{
    __shared__ float sx[SEQT];
    // Permuted raw-gate buffer: slot(r) = (r & ~15) + ((r&7)<<1) + ((r>>3)&1)
    __shared__ __align__(16) float sg[4 * HID];
    // h in B-FRAGMENT ORDER: u32 slot (kk*8 + tg*2 + b3) = half2 for
    // k = 16kk + 8*b3 + 2tg (+1). b0/b1 of one k-step are adjacent -> LDS.64.
    __shared__ __align__(16) unsigned shB_hi[64]; // 128 halves (h high part)
    __shared__ __align__(16) unsigned shB_lo[64]; // 128 halves (h residual)
    __shared__ float stap[HID];                   // fc tap partials (fcw*h)

    const int tid = threadIdx.x;
    const int b   = blockIdx.x;
    const int w   = tid >> 5;          // warp 0..7
    const int l   = tid & 31;
    const int gid = l >> 2;            // 0..7  (frag row group / B column)
    const int tg  = l & 3;             // 0..3
    const bool combiner = (w >= 4);    // warps 4-7 run the cell combine
    const int  cu = tid - 128;         // combiner's hidden unit (0..127)

    // ---------------- Prologue: A fragments (W_hh fp16, resident in RF) ----
    // Warp w owns 4 tiles: gate rows R..R+15, R = 64w + 16t, t = 0..3.
    unsigned Afrag[4][8][4];
#pragma unroll
    for (int t = 0; t < 4; ++t) {
        const int R = 64 * w + 16 * t;
        const float* r0 = W_hh + (R + gid)     * HID;
        const float* r8 = W_hh + (R + gid + 8) * HID;
#pragma unroll
        for (int kk = 0; kk < 8; ++kk) {
            const int k0 = 16 * kk + 2 * tg;
            Afrag[t][kk][0] = pack_h2(r0[k0],     r0[k0 + 1]);
            Afrag[t][kk][1] = pack_h2(r8[k0],     r8[k0 + 1]);
            Afrag[t][kk][2] = pack_h2(r0[k0 + 8], r0[k0 + 9]);
            Afrag[t][kk][3] = pack_h2(r8[k0 + 8], r8[k0 + 9]);
        }
    }

    // Per-lane bias / W_ih for rows (gid, gid+8) of each tile (used at tg==0)
    float biasr[4][2], wihr[4][2];
#pragma unroll
    for (int t = 0; t < 4; ++t) {
        const int R = 64 * w + 16 * t;
        biasr[t][0] = b_ih[R + gid]     + b_hh[R + gid];
        biasr[t][1] = b_ih[R + gid + 8] + b_hh[R + gid + 8];
        wihr[t][0]  = W_ih[R + gid];
        wihr[t][1]  = W_ih[R + gid + 8];
    }

    const float fcw = combiner ? fc_W[cu] : 0.f;
    const float fcb = fc_b[0];
    float c_state = 0.f;

    if (tid < 64) { shB_hi[tid] = 0u; shB_lo[tid] = 0u; }    // h0 = 0
    sx[tid] = x[b * SEQT + tid];                             // 256 threads = SEQT
    if (tid < WIN)  out[b * SEQT + tid] = x[b * SEQT + tid];
    __syncthreads();

    // Combiner's h-store byte offset in the fragment-ordered buffer:
    //   kk=cu>>4, b3=(cu>>3)&1, tg=(cu>>1)&3, e=cu&1
    const int frag_off = combiner
        ? (((cu >> 4) << 5) + (((cu >> 1) & 3) << 3) + (((cu >> 3) & 1) << 2) + ((cu & 1) << 1))
        : 0;
    __half* sthi = (__half*)((char*)shB_hi + frag_off);
    __half* stlo = (__half*)((char*)shB_lo + frag_off);

    // Combiner's permuted gate-slot index: q = slot(cu); gates at q + 128*g.
    const int q = combiner
        ? ((cu & ~15) + ((cu & 7) << 1) + ((cu >> 3) & 1))
        : 0;

    // Producer's paired-store slot (float2 index)
    float2* sg2 = (float2*)sg;

    // B-operand base: column gid==1 reads h_lo; all others read h_hi
    const char* bpc = (const char*)((gid == 1) ? shB_lo : shB_hi);

    // Prefetched per-step init: x*W_ih + bias for this lane's rows
    float init_[4][2];
    {
        const float xt0 = sx[0];
#pragma unroll
        for (int t = 0; t < 4; ++t) {
            init_[t][0] = __fmaf_rn(xt0, wihr[t][0], biasr[t][0]);
            init_[t][1] = __fmaf_rn(xt0, wihr[t][1], biasr[t][1]);
        }
    }

    // ---------------- 3840 chained steps -----------------------------------
    for (int s = 0; s < NSTEP; ++s) {
        // Eight half-depth chains: cA[t] (kk 0..3) + cB[t] (kk 4..7), t=0..3.
        float cA[4][4], cB[4][4];
#pragma unroll
        for (int t = 0; t < 4; ++t) {
            if (tg == 0) { cA[t][0] = init_[t][0]; cA[t][2] = init_[t][1]; }
            else         { cA[t][0] = 0.f;         cA[t][2] = 0.f; }
            cA[t][1] = 0.f; cA[t][3] = 0.f;
            cB[t][0] = 0.f; cB[t][1] = 0.f; cB[t][2] = 0.f; cB[t][3] = 0.f;
        }

        // One LDS.64 per k-step fetches {b0, b1}; 4 MMAs (one per tile) each.
#pragma unroll
        for (int kk = 0; kk < 4; ++kk) {
            const uint2 bb = *(const uint2*)(bpc + kk * 32 + tg * 8);
            mma16816(cA[0], Afrag[0][kk], bb.x, bb.y);
            mma16816(cA[1], Afrag[1][kk], bb.x, bb.y);
            mma16816(cA[2], Afrag[2][kk], bb.x, bb.y);
            mma16816(cA[3], Afrag[3][kk], bb.x, bb.y);
        }
#pragma unroll
        for (int kk = 4; kk < 8; ++kk) {
            const uint2 bb = *(const uint2*)(bpc + kk * 32 + tg * 8);
            mma16816(cB[0], Afrag[0][kk], bb.x, bb.y);
            mma16816(cB[1], Afrag[1][kk], bb.x, bb.y);
            mma16816(cB[2], Afrag[2][kk], bb.x, bb.y);
            mma16816(cB[3], Afrag[3][kk], bb.x, bb.y);
        }

        // tg==0 lanes: raw gate = (col0 hi) + (col1 lo); one STS.64 per tile.
        if (tg == 0) {
#pragma unroll
            for (int t = 0; t < 4; ++t) {
                const float v0 = (cA[t][0] + cB[t][0]) + (cA[t][1] + cB[t][1]);
                const float v1 = (cA[t][2] + cB[t][2]) + (cA[t][3] + cB[t][3]);
                sg2[32 * w + 8 * t + gid] = make_float2(v0, v1);
            }
        }

        // Prefetch next step's init (h-independent) before blocking.
        {
            const int s1 = s + 1;
            const float xt1 = sx[(s1 >> 4) + (s1 & (WIN - 1))];
#pragma unroll
            for (int t = 0; t < 4; ++t) {
                init_[t][0] = __fmaf_rn(xt1, wihr[t][0], biasr[t][0]);
                init_[t][1] = __fmaf_rn(xt1, wihr[t][1], biasr[t][1]);
            }
        }

        const bool tap = ((s & (WIN - 1)) == (WIN - 1));

        if (!combiner) {
            // Producers: post sg, then block once until h is ready.
            BAR_ARRIVE(1);
            BAR_SYNC(2);
        } else {
            // Combiners (warps 4-7, highest arbiter priority): wait for sg.
            BAR_SYNC(1);

            const float gi = sg[q];
            const float gf = sg[q + HID];
            const float gg = sg[q + 2 * HID];
            const float go = sg[q + 3 * HID];
            c_state = sigm_fast(gf) * c_state + sigm_fast(gi) * tanh_fast(gg);
            const float h = sigm_fast(go) * tanh_fast(c_state);

            // Truncation split: hi has 10-bit mantissa (exact in fp16),
            // lo = h - hi exact; the two converts run in parallel.
            const float hi_f = __uint_as_float(__float_as_uint(h) & 0xFFFFE000u);
            const float lo_f = h - hi_f;
            *sthi = __float2half_rn(hi_f);
            *stlo = __float2half_rn(lo_f);

            if (tap) stap[cu] = fcw * h;      // 1 STS; reduce deferred past bar2

            BAR_SYNC(2);

            // Deferred fc-tap reduce: warp 4 only, overlapped with the other
            // warps' next-step MMA issue.
            if (tap && w == 4) {
                float p = stap[l] + stap[l + 32] + stap[l + 64] + stap[l + 96];
                p += __shfl_down_sync(0xffffffffu, p, 16);
                p += __shfl_down_sync(0xffffffffu, p, 8);
                p += __shfl_down_sync(0xffffffffu, p, 4);
                p += __shfl_down_sync(0xffffffffu, p, 2);
                p += __shfl_down_sync(0xffffffffu, p, 1);
                if (l == 0) {
                    const float v = p + fcb;
                    out[b * SEQT + WIN + (s >> 4)] = (v >= 0.f) ? v : 0.3f * v;
                }
            }
        }
    }
}

extern "C" void kernel_launch(void* const* d_in, const int* in_sizes, int n_in,
                              void* d_out, int out_size)
{
    const float* x    = (const float*)d_in[0];
    const float* W_ih = (const float*)d_in[1];
    const float* W_hh = (const float*)d_in[2];
    const float* b_ih = (const float*)d_in[3];
    const float* b_hh = (const float*)d_in[4];
    const float* fc_W = (const float*)d_in[5];
    const float* fc_b = (const float*)d_in[6];

    lstm_mma12_kernel<<<BATCH, NTHREADS>>>(
        x, W_ih, W_hh, b_ih, b_hh, fc_W, fc_b, (float*)d_out);
}